// round 5
// baseline (speedup 1.0000x reference)
#include <cuda_runtime.h>
#include <math.h>

#define BB 32
#define NN 64
#define EE 4096      // NN*NN
#define HID 256
#define NL 9
#define LPAD 260     // padded row stride for 64x256 smem tile (float4-aligned)

// ---------------- device scratch (no allocations allowed) ----------------
__device__ float g_h[2][BB * NN * HID];   // ping-pong node features
__device__ float g_x[2][BB * NN * 3];     // ping-pong coordinates
__device__ float g_din[BB * EE];          // fixed initial pairwise distances (masked)
__device__ float g_P[4][BB * NN * HID];   // h@Wa, h@Wb (edge MLP), h@Xa, h@Xb (coord MLP)
__device__ float g_em[BB * NN * HID];     // aggregated edge messages per node

__device__ __forceinline__ float siluf(float v) { return v / (1.f + __expf(-v)); }
__device__ __forceinline__ float sigmf_(float v) { return 1.f / (1.f + __expf(-v)); }

// ---------------- h0 = [h_in, t] @ win_w + win_b ; copy x ----------------
__global__ void k_init(const float* __restrict__ h_in, const float* __restrict__ t,
                       const float* __restrict__ win_w, const float* __restrict__ win_b,
                       const float* __restrict__ x_in) {
    int row = blockIdx.x;      // b*NN + node
    int n = threadIdx.x;       // 0..255
    __shared__ float sf[6];
    if (n < 5) sf[n] = h_in[row * 5 + n];
    else if (n == 5) sf[5] = t[row];
    __syncthreads();
    float acc = win_b[n];
#pragma unroll
    for (int k = 0; k < 6; k++) acc = fmaf(sf[k], win_w[k * HID + n], acc);
    g_h[0][row * HID + n] = acc;
    if (n < 3) g_x[0][row * 3 + n] = x_in[row * 3 + n];
}

// ---------------- d_in = ||x_i - x_j|| * edge_mask (from initial coords) ----------------
__global__ void k_din(const float* __restrict__ x_in, const float* __restrict__ edge_mask) {
    int ge = blockIdx.x * blockDim.x + threadIdx.x;   // < BB*EE
    int b = ge >> 12;
    int e = ge & 4095;
    int i = e >> 6, j = e & 63;
    float s = 0.f;
#pragma unroll
    for (int k = 0; k < 3; k++) {
        float d = x_in[(b * NN + i) * 3 + k] - x_in[(b * NN + j) * 3 + k];
        s = fmaf(d, d, s);
    }
    g_din[ge] = sqrtf(fmaxf(s, 1e-12f)) * edge_mask[ge];
}

// ---------------- per-layer node projections: 4 GEMMs (2048x256x256) ----------------
__global__ void k_proj(int l, int cur,
                       const float* __restrict__ we_w1, const float* __restrict__ wx_w1) {
    int r0 = blockIdx.x * 16;   // 16 node-rows per CTA
    int mat = blockIdx.y;       // 0: we Wa, 1: we Wb, 2: wx Wa, 3: wx Wb
    const float* W;
    if (mat == 0)      W = we_w1 + (size_t)l * 514 * HID;
    else if (mat == 1) W = we_w1 + (size_t)l * 514 * HID + HID * HID;
    else if (mat == 2) W = wx_w1 + (size_t)l * 514 * HID;
    else               W = wx_w1 + (size_t)l * 514 * HID + HID * HID;
    const float* h = g_h[cur];
    __shared__ float sh[16][HID];
    int tid = threadIdx.x;
    for (int idx = tid; idx < 16 * HID; idx += 256)
        sh[idx >> 8][idx & 255] = h[(r0 + (idx >> 8)) * HID + (idx & 255)];
    __syncthreads();
    float acc[16];
#pragma unroll
    for (int r = 0; r < 16; r++) acc[r] = 0.f;
    for (int k = 0; k < HID; k++) {
        float w = W[k * HID + tid];
#pragma unroll
        for (int r = 0; r < 16; r++) acc[r] = fmaf(sh[r][k], w, acc[r]);
    }
    float* P = g_P[mat];
#pragma unroll
    for (int r = 0; r < 16; r++) P[(r0 + r) * HID + tid] = acc[r];
}

// ---------------- edge kernel: one CTA per (b,i), branch y: 0=message, 1=coords ----------------
#define EDGE_SMEM_FLOATS (64 * LPAD + 4 * HID + 5 * 64 + 192)
#define EDGE_SMEM_BYTES (EDGE_SMEM_FLOATS * 4)

__global__ void __launch_bounds__(256) k_edge(int l, int cur,
        const float* __restrict__ we_w1, const float* __restrict__ we_b1,
        const float* __restrict__ we_w2, const float* __restrict__ we_b2,
        const float* __restrict__ attn_w, const float* __restrict__ attn_b,
        const float* __restrict__ wx_w1, const float* __restrict__ wx_b1,
        const float* __restrict__ wx_w2, const float* __restrict__ wx_b2,
        const float* __restrict__ wx_w3,
        const float* __restrict__ edge_mask, const float* __restrict__ node_mask) {
    extern __shared__ float es[];
    float* L     = es;
    float* sPi   = es + 64 * LPAD;
    float* sw0   = sPi + HID;
    float* sw1   = sw0 + HID;
    float* sb1   = sw1 + HID;
    float* sd2   = sb1 + HID;
    float* sdin  = sd2 + 64;
    float* smask = sdin + 64;
    float* sdv   = smask + 64;
    float* sa    = sdv + 64;
    float* sdiff = sa + 64;

    int bi = blockIdx.x;          // b*NN + i
    int b = bi >> 6, i = bi & 63;
    int br = blockIdx.y;          // 0 = message branch, 1 = coordinate branch
    int tid = threadIdx.x;

    const float* W1 = (br ? wx_w1 : we_w1) + (size_t)l * 514 * HID;
    const float* b1 = (br ? wx_b1 : we_b1) + l * HID;
    const float* W2 = (br ? wx_w2 : we_w2) + (size_t)l * HID * HID;
    const float* b2 = (br ? wx_b2 : we_b2) + l * HID;
    const float* Pi = g_P[br * 2];
    const float* Pj = g_P[br * 2 + 1];
    const float* x  = g_x[cur];

    sPi[tid] = Pi[bi * HID + tid];
    sw0[tid] = W1[512 * HID + tid];   // row for d^2
    sw1[tid] = W1[513 * HID + tid];   // row for d_in
    sb1[tid] = b1[tid];
    if (tid < 64) {
        int j = tid;
        float m = edge_mask[b * EE + i * NN + j];
        float ss = 0.f;
#pragma unroll
        for (int k = 0; k < 3; k++) {
            float dk = (x[(b * NN + i) * 3 + k] - x[(b * NN + j) * 3 + k]) * m;
            sdiff[j * 3 + k] = dk;
            ss = fmaf(dk, dk, ss);
        }
        ss = fmaxf(ss, 1e-12f);
        sd2[j] = ss;
        sdv[j] = sqrtf(ss);
        sdin[j] = g_din[b * EE + i * NN + j];
        smask[j] = m;
    }
    __syncthreads();

    // Phase B: L[j][c] = silu( mask*(Pi + Pj + d2*w512 + din*w513) + b1 )
    for (int j = 0; j < 64; j++) {
        float pre = sPi[tid] + Pj[(b * NN + j) * HID + tid];
        pre = fmaf(sd2[j], sw0[tid], pre);
        pre = fmaf(sdin[j], sw1[tid], pre);
        pre = fmaf(smask[j], pre, sb1[tid]);
        L[j * LPAD + tid] = siluf(pre);
    }
    __syncthreads();

    // Phase C: 64x256x256 GEMM, thread tid owns output column n=tid for all 64 j
    float acc[64];
#pragma unroll
    for (int j = 0; j < 64; j++) acc[j] = 0.f;
    for (int c = 0; c < HID; c += 4) {
        float w0 = W2[(c + 0) * HID + tid];
        float w1v = W2[(c + 1) * HID + tid];
        float w2v = W2[(c + 2) * HID + tid];
        float w3v = W2[(c + 3) * HID + tid];
#pragma unroll
        for (int j = 0; j < 64; j++) {
            float4 lv = *reinterpret_cast<const float4*>(&L[j * LPAD + c]);
            float a = acc[j];
            a = fmaf(lv.x, w0, a);
            a = fmaf(lv.y, w1v, a);
            a = fmaf(lv.z, w2v, a);
            a = fmaf(lv.w, w3v, a);
            acc[j] = a;
        }
    }
    float b2v = b2[tid];
    __syncthreads();   // everyone done reading L before overwrite

    if (br == 0) {
        // m = silu(out + b2); a = sigmoid(m . aw + ab); em[i] = sum_j a_j * m_j
#pragma unroll
        for (int j = 0; j < 64; j++) L[j * LPAD + tid] = siluf(acc[j] + b2v);
        sw0[tid] = attn_w[l * HID + tid];
        __syncthreads();
        if (tid < 64) {
            float a = attn_b[l];
            for (int n = 0; n < HID; n++) a = fmaf(L[tid * LPAD + n], sw0[n], a);
            sa[tid] = sigmf_(a);
        }
        __syncthreads();
        float s = 0.f;
        for (int j = 0; j < 64; j++) s = fmaf(sa[j], L[j * LPAD + tid], s);
        g_em[bi * HID + tid] = s;
    } else {
        // s = silu(out + b2) @ xw3 (no bias); x_new = (x + sum_j diff/(d+1)*s) * node_mask
#pragma unroll
        for (int j = 0; j < 64; j++) L[j * LPAD + tid] = siluf(acc[j] + b2v);
        sw0[tid] = wx_w3[l * HID + tid];
        __syncthreads();
        if (tid < 64) {
            float s = 0.f;
            for (int n = 0; n < HID; n++) s = fmaf(L[tid * LPAD + n], sw0[n], s);
            sa[tid] = s;
        }
        __syncthreads();
        if (tid < 3) {
            float accx = 0.f;
            for (int j = 0; j < 64; j++)
                accx = fmaf(sdiff[j * 3 + tid] / (sdv[j] + 1.f), sa[j], accx);
            g_x[1 - cur][bi * 3 + tid] = (x[bi * 3 + tid] + accx) * node_mask[bi];
        }
    }
}

// ---------------- node MLP: h_new = (h + MLP([h, em])) * node_mask ----------------
__global__ void k_hupd(int l, int cur,
        const float* __restrict__ wh_w1, const float* __restrict__ wh_b1,
        const float* __restrict__ wh_w2, const float* __restrict__ wh_b2,
        const float* __restrict__ node_mask) {
    int r0 = blockIdx.x * 16;
    int tid = threadIdx.x;
    __shared__ float sin_[16][512];
    __shared__ float shid[16][HID];
    const float* h = g_h[cur];
    for (int idx = tid; idx < 16 * 512; idx += 256) {
        int r = idx >> 9, k = idx & 511;
        sin_[r][k] = (k < HID) ? h[(r0 + r) * HID + k] : g_em[(r0 + r) * HID + (k - HID)];
    }
    __syncthreads();
    const float* W1 = wh_w1 + (size_t)l * 512 * HID;
    const float* W2 = wh_w2 + (size_t)l * HID * HID;
    float b1v = wh_b1[l * HID + tid];
    float acc[16];
#pragma unroll
    for (int r = 0; r < 16; r++) acc[r] = 0.f;
    for (int k = 0; k < 512; k++) {
        float w = W1[k * HID + tid];
#pragma unroll
        for (int r = 0; r < 16; r++) acc[r] = fmaf(sin_[r][k], w, acc[r]);
    }
#pragma unroll
    for (int r = 0; r < 16; r++) shid[r][tid] = siluf(acc[r] + b1v);
    __syncthreads();
    float b2v = wh_b2[l * HID + tid];
#pragma unroll
    for (int r = 0; r < 16; r++) acc[r] = 0.f;
    for (int k = 0; k < HID; k++) {
        float w = W2[k * HID + tid];
#pragma unroll
        for (int r = 0; r < 16; r++) acc[r] = fmaf(shid[r][k], w, acc[r]);
    }
    float* ho = g_h[1 - cur];
#pragma unroll
    for (int r = 0; r < 16; r++) {
        int row = r0 + r;
        ho[row * HID + tid] = (h[row * HID + tid] + acc[r] + b2v) * node_mask[row];
    }
}

// ---------------- final: remove-mean on (x - x_in), h @ wout, pack output ----------------
__global__ void k_final(const float* __restrict__ x_in, const float* __restrict__ node_mask,
                        const float* __restrict__ wout_w, const float* __restrict__ wout_b,
                        float* __restrict__ out, int fin) {
    int b = blockIdx.x, tid = threadIdx.x;
    __shared__ float sxd[NN][3];
    __shared__ float smean[3];
    const float* x = g_x[fin];
    const float* h = g_h[fin];
    if (tid < NN) {
        float m = node_mask[b * NN + tid];
#pragma unroll
        for (int k = 0; k < 3; k++)
            sxd[tid][k] = (x[(b * NN + tid) * 3 + k] - x_in[(b * NN + tid) * 3 + k]) * m;
    }
    __syncthreads();
    if (tid < 3) {
        float s = 0.f, n = 0.f;
        for (int nd = 0; nd < NN; nd++) { s += sxd[nd][tid]; n += node_mask[b * NN + nd]; }
        smean[tid] = s / n;
    }
    __syncthreads();
    if (tid < NN) {
        float m = node_mask[b * NN + tid];
#pragma unroll
        for (int k = 0; k < 3; k++)
            out[(b * NN + tid) * 8 + k] = (sxd[tid][k] - smean[k]) * m;
    }
    for (int p = tid; p < NN * 5; p += 256) {
        int nd = p / 5, c = p % 5;
        float accv = wout_b[c];
        const float* hr = &h[(b * NN + nd) * HID];
        for (int k = 0; k < HID; k++) accv = fmaf(hr[k], wout_w[k * 6 + c], accv);
        out[(b * NN + nd) * 8 + 3 + c] = accv * node_mask[b * NN + nd];
    }
}

// ---------------- host launcher ----------------
extern "C" void kernel_launch(void* const* d_in, const int* in_sizes, int n_in,
                              void* d_out, int out_size) {
    const float* x_in      = (const float*)d_in[0];
    const float* h_in      = (const float*)d_in[1];
    const float* t         = (const float*)d_in[2];
    const float* node_mask = (const float*)d_in[3];
    const float* edge_mask = (const float*)d_in[4];
    // d_in[5] = edge_indices (all-pairs meshgrid; structure exploited directly)
    const float* win_w  = (const float*)d_in[6];
    const float* win_b  = (const float*)d_in[7];
    const float* wout_w = (const float*)d_in[8];
    const float* wout_b = (const float*)d_in[9];
    const float* we_w1  = (const float*)d_in[10];
    const float* we_b1  = (const float*)d_in[11];
    const float* we_w2  = (const float*)d_in[12];
    const float* we_b2  = (const float*)d_in[13];
    const float* attn_w = (const float*)d_in[14];
    const float* attn_b = (const float*)d_in[15];
    const float* wh_w1  = (const float*)d_in[16];
    const float* wh_b1  = (const float*)d_in[17];
    const float* wh_w2  = (const float*)d_in[18];
    const float* wh_b2  = (const float*)d_in[19];
    const float* wx_w1  = (const float*)d_in[20];
    const float* wx_b1  = (const float*)d_in[21];
    const float* wx_w2  = (const float*)d_in[22];
    const float* wx_b2  = (const float*)d_in[23];
    const float* wx_w3  = (const float*)d_in[24];
    float* out = (float*)d_out;

    cudaFuncSetAttribute(k_edge, cudaFuncAttributeMaxDynamicSharedMemorySize, EDGE_SMEM_BYTES);

    k_init<<<BB * NN, 256>>>(h_in, t, win_w, win_b, x_in);
    k_din<<<BB * EE / 256, 256>>>(x_in, edge_mask);

    for (int l = 0; l < NL; l++) {
        int cur = l & 1;
        k_proj<<<dim3(BB * NN / 16, 4), 256>>>(l, cur, we_w1, wx_w1);
        k_edge<<<dim3(BB * NN, 2), 256, EDGE_SMEM_BYTES>>>(l, cur,
            we_w1, we_b1, we_w2, we_b2, attn_w, attn_b,
            wx_w1, wx_b1, wx_w2, wx_b2, wx_w3, edge_mask, node_mask);
        k_hupd<<<BB * NN / 16, 256>>>(l, cur, wh_w1, wh_b1, wh_w2, wh_b2, node_mask);
    }
    // 9 layers: final state lives in buffer index 1
    k_final<<<BB, 256>>>(x_in, node_mask, wout_w, wout_b, out, 1);
}